// round 1
// baseline (speedup 1.0000x reference)
#include <cuda_runtime.h>
#include <cuda_bf16.h>

// Problem shape (fixed by the reference):
//   anchors:  (N=1024, 2) float32
//   gt_boxes: (B=128, M=256, 4) float32
// Outputs (tuple order): matches (B, M) argmax over N, then ious (B, N, M).
// d_out is float32: [matches (32768) | ious (33554432)].
#define N_ANCH 1024
#define B_     128
#define M_     256
#define NCHUNK 4
#define NC     (N_ANCH / NCHUNK)   // 256 anchors per chunk

// Scratch for cross-chunk argmax combine (no cudaMalloc allowed).
__device__ float g_pmax[NCHUNK * B_ * M_];
__device__ int   g_pidx[NCHUNK * B_ * M_];

// Grid: (B, NCHUNK). Block: 256 threads, thread t = m.
// Each thread: fixed (b, m); loop its 256-anchor chunk from smem (broadcast,
// conflict-free), write iou[b][n][m] (128B contiguous per warp per n), and
// track chunk-local argmax with strictly-greater updates (first-max wins).
__global__ void __launch_bounds__(256)
iou_kernel(const float* __restrict__ anchors,
           const float* __restrict__ gt,
           float* __restrict__ ious)
{
    __shared__ float4 sA[NC];   // {aw, ah, aw*ah, pad}

    const int b = blockIdx.x;
    const int c = blockIdx.y;
    const int m = threadIdx.x;

    for (int i = threadIdx.x; i < NC; i += 256) {
        const int n = c * NC + i;
        const float aw = anchors[2 * n];
        const float ah = anchors[2 * n + 1];
        sA[i] = make_float4(aw, ah, aw * ah, 0.0f);
    }
    __syncthreads();

    // gt box for this (b, m): [xmin, ymin, xmax, ymax]
    const float4 g  = reinterpret_cast<const float4*>(gt)[b * M_ + m];
    const float gw  = g.z - g.x;
    const float gh  = g.w - g.y;
    const float areaB = gw * gh;

    float best  = -1.0f;
    int   bestn = 0;

    float* outp = ious + (size_t)b * N_ANCH * M_ + (size_t)c * NC * M_ + m;

    #pragma unroll 8
    for (int i = 0; i < NC; i++) {
        const float4 a = sA[i];
        // Centered boxes: iw = min(aw, gw), ih = min(ah, gh) -- bitwise equal
        // to the reference's clip(min(r)-max(l)) since 0.5*w is exact and
        // 0.5m+0.5m == m; clips are dead (0.05 <= sizes <= 1.0).
        const float iw    = fminf(a.x, gw);
        const float ih    = fminf(a.y, gh);
        const float inter = iw * ih;
        // Same association order as reference: (area_a + area_b) - inter.
        const float uni   = (a.z + areaB) - inter;
        // IEEE division: bit-identical ious to the reference -> exact argmax.
        const float iou   = inter / uni;
        outp[(size_t)i * M_] = iou;
        if (iou > best) { best = iou; bestn = i; }
    }

    const int slot = (c * B_ + b) * M_ + m;  // chunk-major partials
    g_pmax[slot] = best;
    g_pidx[slot] = c * NC + bestn;
}

// Fold the NCHUNK partial argmaxes per (b, m). Ascending chunk order with
// strictly-greater updates preserves jnp.argmax first-max tie-breaking.
__global__ void __launch_bounds__(256)
reduce_kernel(float* __restrict__ matches)
{
    const int t = blockIdx.x * blockDim.x + threadIdx.x;  // t = b*M + m
    float best  = g_pmax[t];
    int   besti = g_pidx[t];
    #pragma unroll
    for (int c = 1; c < NCHUNK; c++) {
        const float v = g_pmax[c * (B_ * M_) + t];
        const int   x = g_pidx[c * (B_ * M_) + t];
        if (v > best) { best = v; besti = x; }
    }
    matches[t] = (float)besti;
}

extern "C" void kernel_launch(void* const* d_in, const int* in_sizes, int n_in,
                              void* d_out, int out_size)
{
    const float* anchors = (const float*)d_in[0];
    const float* gt      = (const float*)d_in[1];
    float* out = (float*)d_out;

    // ious live after the matches block; derive offset from out_size so any
    // harness-side padding convention still lands the tail correctly.
    const size_t ious_elems = (size_t)B_ * N_ANCH * M_;
    const size_t ious_off   = (size_t)out_size - ious_elems;

    iou_kernel<<<dim3(B_, NCHUNK), 256>>>(anchors, gt, out + ious_off);
    reduce_kernel<<<B_ * M_ / 256, 256>>>(out);
}

// round 2
// speedup vs baseline: 1.1366x; 1.1366x over previous
#include <cuda_runtime.h>
#include <cuda_bf16.h>

// Shapes fixed by the reference:
//   anchors:  (N=1024, 2) f32;  gt_boxes: (B=128, M=256, 4) f32
// Outputs (tuple order): matches (B,M) then ious (B,N,M), both f32 in d_out.
#define N_ANCH 1024
#define B_     128
#define M_     256

#define M_PER_CTA   64          // m-slice per CTA
#define NQ          16          // m-quads per CTA (64 / 4)
#define NCH         16          // anchor chunks per CTA
#define CH          (N_ANCH / NCH)   // 64 anchors per chunk

// One fused kernel. Grid (B, M/64), block 256.
//   tid -> mq = tid & 15  (handles m = mbase + 4*mq .. +3, one float4 store)
//          ch = tid >> 4  (anchor chunk ch*64 .. ch*64+63)
// Each thread: 64 anchors x 4 m's; STG.128 per anchor; per-m argmax partials
// combined in smem (ascending chunk, strictly-greater => jnp.argmax first-max).
__global__ void __launch_bounds__(256)
matcher_kernel(const float* __restrict__ anchors,
               const float* __restrict__ gt,
               float* __restrict__ matches,
               float* __restrict__ ious)
{
    __shared__ float4 sA[N_ANCH];            // {aw, ah, aw*ah, 0}  (16 KB)
    __shared__ float  sPm[NCH][M_PER_CTA];   // per-chunk best iou   (4 KB)
    __shared__ int    sPi[NCH][M_PER_CTA];   // per-chunk best n     (4 KB)

    const int tid = threadIdx.x;
    const int mq  = tid & (NQ - 1);
    const int ch  = tid >> 4;
    const int b     = blockIdx.x;
    const int mbase = blockIdx.y * M_PER_CTA;
    const int m0    = mbase + 4 * mq;        // first of this thread's 4 m's

    // Stage all anchors once (widths/heights + area). Boxes are centered, so
    // iw = min(aw,gw) exactly (0.5w exact in fp32; clips dead: 0.05<=w<=1).
    for (int i = tid; i < N_ANCH; i += 256) {
        const float2 a = reinterpret_cast<const float2*>(anchors)[i];
        sA[i] = make_float4(a.x, a.y, a.x * a.y, 0.0f);
    }
    __syncthreads();

    // Load this thread's 4 gt boxes.
    float gw[4], gh[4], areaB[4];
    #pragma unroll
    for (int j = 0; j < 4; j++) {
        const float4 g = reinterpret_cast<const float4*>(gt)[b * M_ + m0 + j];
        gw[j] = g.z - g.x;
        gh[j] = g.w - g.y;
        areaB[j] = gw[j] * gh[j];
    }

    float best[4]  = {-1.0f, -1.0f, -1.0f, -1.0f};
    int   bestn[4] = {0, 0, 0, 0};

    // ious[b][n][m0..m0+3] as float4; n = ch*CH + i; row stride M_ floats.
    float4* p = reinterpret_cast<float4*>(
        ious + (size_t)b * N_ANCH * M_ + (size_t)ch * CH * M_ + m0);

    #pragma unroll 4
    for (int i = 0; i < CH; i++) {
        const float4 a = sA[ch * CH + i];
        float4 v;
        float r[4];
        #pragma unroll
        for (int j = 0; j < 4; j++) {
            const float iw    = fminf(a.x, gw[j]);
            const float ih    = fminf(a.y, gh[j]);
            const float inter = iw * ih;
            // Same association order as the reference: (areaA+areaB)-inter.
            const float uni   = (a.z + areaB[j]) - inter;
            r[j] = inter / uni;            // IEEE div: bit-identical ious
        }
        v.x = r[0]; v.y = r[1]; v.z = r[2]; v.w = r[3];
        *p = v;
        p += M_ / 4;
        #pragma unroll
        for (int j = 0; j < 4; j++)
            if (r[j] > best[j]) { best[j] = r[j]; bestn[j] = i; }
    }

    // Publish per-chunk partials, then fold across chunks (ascending => the
    // first-occurring max wins, matching jnp.argmax exactly).
    #pragma unroll
    for (int j = 0; j < 4; j++) {
        sPm[ch][4 * mq + j] = best[j];
        sPi[ch][4 * mq + j] = ch * CH + bestn[j];
    }
    __syncthreads();

    if (tid < M_PER_CTA) {
        float bv = sPm[0][tid];
        int   bi = sPi[0][tid];
        #pragma unroll
        for (int c = 1; c < NCH; c++) {
            const float v = sPm[c][tid];
            if (v > bv) { bv = v; bi = sPi[c][tid]; }
        }
        matches[b * M_ + mbase + tid] = (float)bi;
    }
}

extern "C" void kernel_launch(void* const* d_in, const int* in_sizes, int n_in,
                              void* d_out, int out_size)
{
    const float* anchors = (const float*)d_in[0];
    const float* gt      = (const float*)d_in[1];
    float* out = (float*)d_out;

    const size_t ious_elems = (size_t)B_ * N_ANCH * M_;
    const size_t ious_off   = (size_t)out_size - ious_elems;

    matcher_kernel<<<dim3(B_, M_ / M_PER_CTA), 256>>>(
        anchors, gt, out, out + ious_off);
}

// round 4
// speedup vs baseline: 1.1720x; 1.0312x over previous
#include <cuda_runtime.h>
#include <cuda_bf16.h>

// Shapes: anchors (N=1024,2) f32; gt_boxes (B=128, M=256, 4) f32.
// Output f32: [matches (B*M) | ious (B,N,M)].
#define N_ANCH 1024
#define B_     128
#define M_     256

#define M_PER_CTA 64
#define NQ        16                 // m-quads per CTA
#define NCH       32                 // anchor chunks per CTA
#define CH        (N_ANCH / NCH)     // 32 anchors per chunk
#define NTHREADS  (NQ * NCH)         // 512

typedef unsigned long long u64;

// ---- packed f32x2 helpers (sm_103a; PTX-only, ptxas never auto-packs) ----
__device__ __forceinline__ u64 pk(float lo, float hi) {
    u64 d; asm("mov.b64 %0, {%1, %2};" : "=l"(d) : "f"(lo), "f"(hi)); return d;
}
__device__ __forceinline__ void upk(u64 v, float& lo, float& hi) {
    asm("mov.b64 {%0, %1}, %2;" : "=f"(lo), "=f"(hi) : "l"(v));
}
__device__ __forceinline__ u64 mul2(u64 a, u64 b) {
    u64 d; asm("mul.rn.f32x2 %0, %1, %2;" : "=l"(d) : "l"(a), "l"(b)); return d;
}
__device__ __forceinline__ u64 add2(u64 a, u64 b) {
    u64 d; asm("add.rn.f32x2 %0, %1, %2;" : "=l"(d) : "l"(a), "l"(b)); return d;
}
__device__ __forceinline__ u64 fma2(u64 a, u64 b, u64 c) {
    u64 d; asm("fma.rn.f32x2 %0, %1, %2, %3;" : "=l"(d) : "l"(a), "l"(b), "l"(c)); return d;
}
__device__ __forceinline__ float rcpa(float x) {
    float r; asm("rcp.approx.f32 %0, %1;" : "=f"(r) : "f"(x)); return r;
}

// Packed correctly-rounded division q = x / (s - x), replicating the exact
// ptxas div.rn fast path (MUFU.RCP + 2 FFMA refinements + residual fixup).
// All operands here are normal and well-scaled (x in [2.5e-3,1], s-x in
// [2.5e-3,2]) so the FCHK slow path of the compiler sequence can never trip:
// this is bit-identical to IEEE div.rn, preserving rel_err == 0 and argmax.
__device__ __forceinline__ u64 iou_div2(u64 x, u64 s) {
    const u64 NEG1 = 0xBF800000BF800000ULL;   // {-1.f, -1.f}
    const u64 ONE  = 0x3F8000003F800000ULL;   // { 1.f,  1.f}
    u64 y  = fma2(x, NEG1, s);                // uni = s - x (single rounding)
    u64 ny = mul2(y, NEG1);                   // -uni (exact)
    float y0, y1; upk(y, y0, y1);
    u64 r  = pk(rcpa(y0), rcpa(y1));          // MUFU.RCP per lane
    u64 e  = fma2(ny, r, ONE);                // 1 - y*r
    r      = fma2(r, e, r);                   // refined reciprocal
    u64 q  = mul2(x, r);
    u64 rem = fma2(ny, q, x);                 // x - y*q
    return fma2(rem, r, q);                   // correctly-rounded quotient
}

// Fused kernel. Grid (B, M/64), block 512.
//   mq = tid & 15 -> m = mbase + 4*mq .. +3 (one 16B store)
//   ch = tid >> 4 -> anchors [ch*32, ch*32+32)
__global__ void __launch_bounds__(NTHREADS)
matcher_kernel(const float* __restrict__ anchors,
               const float* __restrict__ gt,
               float* __restrict__ matches,
               float* __restrict__ ious)
{
    __shared__ float4 sA[N_ANCH];            // {aw, ah, aw*ah, 0}  16 KB
    __shared__ float  sPm[NCH][M_PER_CTA];   // per-chunk best iou   8 KB
    __shared__ int    sPi[NCH][M_PER_CTA];   // per-chunk best n     8 KB

    const int tid = threadIdx.x;
    const int mq  = tid & (NQ - 1);
    const int ch  = tid >> 4;
    const int b     = blockIdx.x;
    const int mbase = blockIdx.y * M_PER_CTA;
    const int m0    = mbase + 4 * mq;

    // Stage anchors. Centered boxes => iw = min(aw, gw) bitwise (0.5w exact;
    // clips dead since 0.05 <= sizes <= 1.0). Validated rel_err=0 in R1/R2.
    for (int i = tid; i < N_ANCH; i += NTHREADS) {
        const float2 a = reinterpret_cast<const float2*>(anchors)[i];
        sA[i] = make_float4(a.x, a.y, a.x * a.y, 0.0f);
    }
    __syncthreads();

    float gw[4], gh[4];
    float aB[4];
    #pragma unroll
    for (int j = 0; j < 4; j++) {
        const float4 g = reinterpret_cast<const float4*>(gt)[b * M_ + m0 + j];
        gw[j] = g.z - g.x;
        gh[j] = g.w - g.y;
        aB[j] = gw[j] * gh[j];
    }
    const u64 aB01 = pk(aB[0], aB[1]);
    const u64 aB23 = pk(aB[2], aB[3]);

    float best[4]  = {-1.0f, -1.0f, -1.0f, -1.0f};
    int   bestn[4] = {0, 0, 0, 0};

    // ious[b][n][m0..m0+3] as one 16B store; row stride M_ floats.
    ulonglong2* pp = reinterpret_cast<ulonglong2*>(
        ious + (size_t)b * N_ANCH * M_ + (size_t)ch * CH * M_ + m0);

    #pragma unroll 4
    for (int i = 0; i < CH; i++) {
        const float4 a = sA[ch * CH + i];
        const u64 az2  = pk(a.z, a.z);
        const u64 iw01 = pk(fminf(a.x, gw[0]), fminf(a.x, gw[1]));
        const u64 ih01 = pk(fminf(a.y, gh[0]), fminf(a.y, gh[1]));
        const u64 iw23 = pk(fminf(a.x, gw[2]), fminf(a.x, gw[3]));
        const u64 ih23 = pk(fminf(a.y, gh[2]), fminf(a.y, gh[3]));
        const u64 x01  = mul2(iw01, ih01);          // inter
        const u64 x23  = mul2(iw23, ih23);
        const u64 s01  = add2(az2, aB01);           // area_a + area_b
        const u64 s23  = add2(az2, aB23);
        const u64 q01  = iou_div2(x01, s01);
        const u64 q23  = iou_div2(x23, s23);

        ulonglong2 st; st.x = q01; st.y = q23;      // little-endian: m0 first
        *pp = st;
        pp += M_ / 4;

        float r0, r1, r2, r3;
        upk(q01, r0, r1); upk(q23, r2, r3);
        if (r0 > best[0]) { best[0] = r0; bestn[0] = i; }
        if (r1 > best[1]) { best[1] = r1; bestn[1] = i; }
        if (r2 > best[2]) { best[2] = r2; bestn[2] = i; }
        if (r3 > best[3]) { best[3] = r3; bestn[3] = i; }
    }

    #pragma unroll
    for (int j = 0; j < 4; j++) {
        sPm[ch][4 * mq + j] = best[j];
        sPi[ch][4 * mq + j] = ch * CH + bestn[j];
    }
    __syncthreads();

    // Fold chunks ascending with strict-greater: first-occurring max wins,
    // exactly matching jnp.argmax tie-breaking.
    if (tid < M_PER_CTA) {
        float bv = sPm[0][tid];
        int   bi = sPi[0][tid];
        #pragma unroll
        for (int c = 1; c < NCH; c++) {
            const float v = sPm[c][tid];
            if (v > bv) { bv = v; bi = sPi[c][tid]; }
        }
        matches[b * M_ + mbase + tid] = (float)bi;
    }
}

extern "C" void kernel_launch(void* const* d_in, const int* in_sizes, int n_in,
                              void* d_out, int out_size)
{
    const float* anchors = (const float*)d_in[0];
    const float* gt      = (const float*)d_in[1];
    float* out = (float*)d_out;

    const size_t ious_elems = (size_t)B_ * N_ANCH * M_;
    const size_t ious_off   = (size_t)out_size - ious_elems;

    matcher_kernel<<<dim3(B_, M_ / M_PER_CTA), NTHREADS>>>(
        anchors, gt, out, out + ious_off);
}

// round 5
// speedup vs baseline: 1.2718x; 1.0851x over previous
#include <cuda_runtime.h>
#include <cuda_bf16.h>

// Shapes: anchors (N=1024,2) f32; gt_boxes (B=128, M=256, 4) f32.
// Output f32: [matches (B*M) | ious (B,N,M)].
#define N_ANCH 1024
#define B_     128
#define M_     256

#define M_PER_CTA 32
#define NQ        8                  // m-quads per CTA (32/4)
#define NCH       32                 // anchor chunks per CTA
#define CH        (N_ANCH / NCH)     // 32 anchors per chunk
#define NTHREADS  (NQ * NCH)         // 256

typedef unsigned long long u64;

// ---- packed f32x2 helpers (sm_103a; PTX-only) ----
__device__ __forceinline__ u64 pk(float lo, float hi) {
    u64 d; asm("mov.b64 %0, {%1, %2};" : "=l"(d) : "f"(lo), "f"(hi)); return d;
}
__device__ __forceinline__ void upk(u64 v, float& lo, float& hi) {
    asm("mov.b64 {%0, %1}, %2;" : "=f"(lo), "=f"(hi) : "l"(v));
}
__device__ __forceinline__ u64 mul2(u64 a, u64 b) {
    u64 d; asm("mul.rn.f32x2 %0, %1, %2;" : "=l"(d) : "l"(a), "l"(b)); return d;
}
__device__ __forceinline__ u64 add2(u64 a, u64 b) {
    u64 d; asm("add.rn.f32x2 %0, %1, %2;" : "=l"(d) : "l"(a), "l"(b)); return d;
}
__device__ __forceinline__ u64 fma2(u64 a, u64 b, u64 c) {
    u64 d; asm("fma.rn.f32x2 %0, %1, %2, %3;" : "=l"(d) : "l"(a), "l"(b), "l"(c)); return d;
}
__device__ __forceinline__ float rcpa(float x) {
    float r; asm("rcp.approx.f32 %0, %1;" : "=f"(r) : "f"(x)); return r;
}

// Packed correctly-rounded q = x / (s - x): exact ptxas div.rn fast path
// (rcp + Newton + residual fixup). Operands here are always normal and
// well-scaled (x in [2.5e-3,1], s-x in [2.5e-3,2]) so the slow path can't
// trip: bit-identical to IEEE div.rn -> rel_err stays 0, argmax exact.
__device__ __forceinline__ u64 iou_div2(u64 x, u64 s) {
    const u64 NEG1 = 0xBF800000BF800000ULL;
    const u64 ONE  = 0x3F8000003F800000ULL;
    u64 y  = fma2(x, NEG1, s);                // uni = s - x
    u64 ny = mul2(y, NEG1);                   // -uni (exact)
    float y0, y1; upk(y, y0, y1);
    u64 r  = pk(rcpa(y0), rcpa(y1));
    u64 e  = fma2(ny, r, ONE);
    r      = fma2(r, e, r);
    u64 q  = mul2(x, r);
    u64 rem = fma2(ny, q, x);
    return fma2(rem, r, q);
}

// Grid (B, M/32) = 1024 CTAs, block 256 -> ~5 CTAs/SM, ~62% occupancy.
//   mq = tid & 7  -> m = mbase + 4*mq .. +3 (one 16B store per anchor)
//   ch = tid >> 3 -> anchors [ch*32, ch*32+32)
__global__ void __launch_bounds__(NTHREADS)
matcher_kernel(const float* __restrict__ anchors,
               const float* __restrict__ gt,
               float* __restrict__ matches,
               float* __restrict__ ious)
{
    __shared__ float2 sWH[N_ANCH];           // {aw, ah}           8 KB
    __shared__ u64    sAZ[N_ANCH];           // {area, area} pair  8 KB
    __shared__ float  sPm[NCH][M_PER_CTA];   // per-chunk best iou 4 KB
    __shared__ int    sPi[NCH][M_PER_CTA];   // per-chunk best n   4 KB

    const int tid = threadIdx.x;
    const int mq  = tid & (NQ - 1);
    const int ch  = tid >> 3;
    const int b     = blockIdx.x;
    const int mbase = blockIdx.y * M_PER_CTA;
    const int m0    = mbase + 4 * mq;

    // Stage anchors once: widths/heights + pre-packed {area,area}.
    // Centered boxes => iw = min(aw,gw) bitwise (0.5w exact; clips dead).
    for (int i = tid; i < N_ANCH; i += NTHREADS) {
        const float2 a = reinterpret_cast<const float2*>(anchors)[i];
        sWH[i] = a;
        const float az = a.x * a.y;
        sAZ[i] = pk(az, az);
    }
    __syncthreads();

    float gw[4], gh[4], aB[4];
    #pragma unroll
    for (int j = 0; j < 4; j++) {
        const float4 g = reinterpret_cast<const float4*>(gt)[b * M_ + m0 + j];
        gw[j] = g.z - g.x;
        gh[j] = g.w - g.y;
        aB[j] = gw[j] * gh[j];
    }
    const u64 aB01 = pk(aB[0], aB[1]);
    const u64 aB23 = pk(aB[2], aB[3]);

    float best[4]  = {-1.0f, -1.0f, -1.0f, -1.0f};
    int   bestn[4] = {0, 0, 0, 0};

    ulonglong2* pp = reinterpret_cast<ulonglong2*>(
        ious + (size_t)b * N_ANCH * M_ + (size_t)ch * CH * M_ + m0);

    #pragma unroll 4
    for (int i = 0; i < CH; i++) {
        const float2 a  = sWH[ch * CH + i];
        const u64    az = sAZ[ch * CH + i];
        const u64 iw01 = pk(fminf(a.x, gw[0]), fminf(a.x, gw[1]));
        const u64 ih01 = pk(fminf(a.y, gh[0]), fminf(a.y, gh[1]));
        const u64 iw23 = pk(fminf(a.x, gw[2]), fminf(a.x, gw[3]));
        const u64 ih23 = pk(fminf(a.y, gh[2]), fminf(a.y, gh[3]));
        const u64 x01  = mul2(iw01, ih01);          // inter
        const u64 x23  = mul2(iw23, ih23);
        const u64 s01  = add2(az, aB01);            // area_a + area_b
        const u64 s23  = add2(az, aB23);
        const u64 q01  = iou_div2(x01, s01);
        const u64 q23  = iou_div2(x23, s23);

        ulonglong2 st; st.x = q01; st.y = q23;
        *pp = st;
        pp += M_ / 4;

        float r0, r1, r2, r3;
        upk(q01, r0, r1); upk(q23, r2, r3);
        if (r0 > best[0]) { best[0] = r0; bestn[0] = i; }
        if (r1 > best[1]) { best[1] = r1; bestn[1] = i; }
        if (r2 > best[2]) { best[2] = r2; bestn[2] = i; }
        if (r3 > best[3]) { best[3] = r3; bestn[3] = i; }
    }

    #pragma unroll
    for (int j = 0; j < 4; j++) {
        sPm[ch][4 * mq + j] = best[j];
        sPi[ch][4 * mq + j] = ch * CH + bestn[j];
    }
    __syncthreads();

    // Fold chunks ascending, strict-greater: first-occurring max wins,
    // matching jnp.argmax exactly.
    if (tid < M_PER_CTA) {
        float bv = sPm[0][tid];
        int   bi = sPi[0][tid];
        #pragma unroll
        for (int c = 1; c < NCH; c++) {
            const float v = sPm[c][tid];
            if (v > bv) { bv = v; bi = sPi[c][tid]; }
        }
        matches[b * M_ + mbase + tid] = (float)bi;
    }
}

extern "C" void kernel_launch(void* const* d_in, const int* in_sizes, int n_in,
                              void* d_out, int out_size)
{
    const float* anchors = (const float*)d_in[0];
    const float* gt      = (const float*)d_in[1];
    float* out = (float*)d_out;

    const size_t ious_elems = (size_t)B_ * N_ANCH * M_;
    const size_t ious_off   = (size_t)out_size - ious_elems;

    matcher_kernel<<<dim3(B_, M_ / M_PER_CTA), NTHREADS>>>(
        anchors, gt, out, out + ious_off);
}